// round 7
// baseline (speedup 1.0000x reference)
#include <cuda_runtime.h>

#define NHEADS 8
#define HDIM   64
#define TNUM   10
#define QDIM   256
#define NCOLS  80        // NHEADS * TNUM
#define NBATCH 131072

#define BM     128
#define BK     16
#define NTILES (QDIM / BK)   // 16
#define TPB    256

#define GPITCH 12            // per-head group pitch in M rows (10 used + 2 pad)
#define MPITCH 96            // 8 groups * 12 floats; 96*4B = 384B, 16B aligned
#define APITCH 129           // transposed A pitch: bank = (k + row) mod 32

// Precomputed fused projection matrix, already in grouped/padded layout:
// M_g[k][ (c/10)*GPITCH + c%10 ],  scores[h,n,t] = sum_k X[n,k]*M[k][h*10+t]
__device__ float M_g[QDIM * MPITCH];

__global__ void precompute_M(const float* __restrict__ embed,
                             const float* __restrict__ Wq,
                             const float* __restrict__ Wk) {
    const int col = blockIdx.x;          // 0..79
    const int h = col / TNUM;
    const int t = col % TNUM;
    __shared__ float kv[HDIM];
    const int tid = threadIdx.x;         // 0..255
    if (tid < HDIM) {
        const int e = h * HDIM + tid;
        float s = 0.f;
        #pragma unroll
        for (int d = 0; d < HDIM; ++d)
            s += tanhf(embed[t * HDIM + d]) * Wk[e * HDIM + d];
        kv[tid] = s;
    }
    __syncthreads();
    float s = 0.f;
    #pragma unroll
    for (int dd = 0; dd < HDIM; ++dd)
        s += Wq[(h * HDIM + dd) * QDIM + tid] * kv[dd];
    M_g[tid * MPITCH + h * GPITCH + t] = s * 0.125f;
}

// ---- packed f32x2 helpers (FFMA2: 2x fp32 FMA throughput on sm_103a) ----
__device__ __forceinline__ unsigned long long splat2(float x) {
    unsigned long long r;
    asm("mov.b64 %0, {%1, %1};" : "=l"(r) : "r"(__float_as_uint(x)));
    return r;
}
__device__ __forceinline__ void fma2(unsigned long long& d,
                                     unsigned long long a,
                                     unsigned long long b) {
    asm("fma.rn.f32x2 %0, %1, %2, %0;" : "+l"(d) : "l"(a), "l"(b));
}
__device__ __forceinline__ float2 unpack2(unsigned long long v) {
    float lo, hi;
    asm("mov.b64 {%0, %1}, %2;" : "=f"(lo), "=f"(hi) : "l"(v));
    return make_float2(lo, hi);
}

__device__ __forceinline__ unsigned smem_u32(const void* p) {
    return (unsigned)__cvta_generic_to_shared(p);
}
__device__ __forceinline__ void cpa4(unsigned dst, const void* src) {
    asm volatile("cp.async.ca.shared.global [%0], [%1], 4;"
                 :: "r"(dst), "l"(src) : "memory");
}
__device__ __forceinline__ void cpa16(unsigned dst, const void* src) {
    asm volatile("cp.async.ca.shared.global [%0], [%1], 16;"
                 :: "r"(dst), "l"(src) : "memory");
}
__device__ __forceinline__ void cpa_commit() {
    asm volatile("cp.async.commit_group;" ::: "memory");
}
__device__ __forceinline__ void cpa_wait_all() {
    asm volatile("cp.async.wait_group 0;" ::: "memory");
}

__global__ __launch_bounds__(TPB, 3)
void fused_attn(const float* __restrict__ X,
                const float* __restrict__ embed,
                float* __restrict__ style,   // [N][512]
                float* __restrict__ attn)    // [8][N][10]
{
    // A transposed: A_sh[buf][k][row], pitch 129 -> conflict-free reads & cp.async writes
    __shared__ __align__(16) float A_sh[2][BK * APITCH];
    // M grouped: M_sh[buf][k][8 groups * 12 floats]; LDS.128 across cg conflict-free
    __shared__ __align__(16) float M_sh[2][BK * MPITCH];
    __shared__ __align__(16) float kr_sh[TNUM * HDIM];

    const int tid = threadIdx.x;
    const int rg = tid >> 3;     // 0..31 : 4 rows each
    const int cg = tid & 7;      // 0..7  : head / 10-col group
    const int rowBase = blockIdx.x * BM;

    for (int i = tid; i < TNUM * HDIM; i += TPB)
        kr_sh[i] = tanhf(embed[i]);

    // ---- cp.async prefetch of one (A,M) tile pair into buffer b ----
    const int ak = tid & 15;          // k within tile
    const int ar0 = tid >> 4;         // 0..15, 16 rows per round
    auto prefetch = [&](int t, int b) {
        const int k0 = t * BK;
        // A tile: 128 rows x 16 k, 4B transposed copies (coalesced gmem reads)
        const float* asrc = X + (size_t)(rowBase + ar0) * QDIM + k0 + ak;
        unsigned abase = smem_u32(&A_sh[b][0]) + (unsigned)(ak * APITCH + ar0) * 4u;
        #pragma unroll
        for (int j = 0; j < 8; ++j)
            cpa4(abase + (unsigned)(j * 16) * 4u, asrc + (size_t)j * 16 * QDIM);
        // M tile: 16 rows x 96 floats = 6144B, 16B copies (layout-preserving)
        const char* msrc = (const char*)(M_g + k0 * MPITCH);
        unsigned mbase = smem_u32(&M_sh[b][0]);
        for (int off = tid * 16; off < BK * MPITCH * 4; off += TPB * 16)
            cpa16(mbase + (unsigned)off, msrc + off);
        cpa_commit();
    };

    unsigned long long acc[4][5];   // 4 rows x 5 col-pairs (10 cols)
    #pragma unroll
    for (int r = 0; r < 4; ++r)
        #pragma unroll
        for (int j = 0; j < 5; ++j)
            acc[r][j] = 0ull;

    prefetch(0, 0);

    for (int t = 0; t < NTILES; ++t) {
        const int buf = t & 1;
        cpa_wait_all();          // tile t resident (this thread's copies)
        __syncthreads();         // all threads' copies visible; prev compute done
        if (t + 1 < NTILES) prefetch(t + 1, buf ^ 1);

        const float* Ab = &A_sh[buf][0];
        const float* Mb = &M_sh[buf][0];
        #pragma unroll
        for (int kk = 0; kk < BK; ++kk) {
            const float* mrow = Mb + kk * MPITCH + cg * GPITCH;
            const ulonglong2 m01 = *(const ulonglong2*)mrow;
            const ulonglong2 m23 = *(const ulonglong2*)(mrow + 4);
            const unsigned long long m4 = *(const unsigned long long*)(mrow + 8);
            const float* arow = Ab + kk * APITCH + rg * 4;
            #pragma unroll
            for (int r = 0; r < 4; ++r) {
                const unsigned long long a2 = splat2(arow[r]);
                fma2(acc[r][0], a2, m01.x);
                fma2(acc[r][1], a2, m01.y);
                fma2(acc[r][2], a2, m23.x);
                fma2(acc[r][3], a2, m23.y);
                fma2(acc[r][4], a2, m4);
            }
        }
    }

    // ---- epilogue: one row at a time (register-lean) ----
    #pragma unroll
    for (int r = 0; r < 4; ++r) {
        float s10[10];
        #pragma unroll
        for (int j = 0; j < 5; ++j) {
            const float2 f = unpack2(acc[r][j]);
            s10[2 * j]     = f.x;
            s10[2 * j + 1] = f.y;
        }
        const size_t n = (size_t)rowBase + rg * 4 + r;

        // attn_score: [h][n][t], h == cg
        float2* ap = (float2*)(attn + (size_t)cg * NBATCH * TNUM + n * TNUM);
        #pragma unroll
        for (int j = 0; j < 5; ++j)
            ap[j] = make_float2(s10[2 * j], s10[2 * j + 1]);

        // style: out[n, cg*64 + d] = sum_t s10[t] * kr[t][d], 16-float chunks
        float* outp = style + n * 512 + cg * 64;
        #pragma unroll
        for (int ch = 0; ch < 4; ++ch) {
            unsigned long long o[8] = {0ull,0ull,0ull,0ull,0ull,0ull,0ull,0ull};
            #pragma unroll
            for (int t = 0; t < TNUM; ++t) {
                const unsigned long long sv = splat2(s10[t]);
                const float* kp = kr_sh + t * HDIM + ch * 16;
                const ulonglong2 ka = *(const ulonglong2*)kp;
                const ulonglong2 kb = *(const ulonglong2*)(kp + 4);
                const ulonglong2 kc = *(const ulonglong2*)(kp + 8);
                const ulonglong2 kd = *(const ulonglong2*)(kp + 12);
                fma2(o[0], sv, ka.x);
                fma2(o[1], sv, ka.y);
                fma2(o[2], sv, kb.x);
                fma2(o[3], sv, kb.y);
                fma2(o[4], sv, kc.x);
                fma2(o[5], sv, kc.y);
                fma2(o[6], sv, kd.x);
                fma2(o[7], sv, kd.y);
            }
            #pragma unroll
            for (int q = 0; q < 4; ++q) {
                const float2 f0 = unpack2(o[2 * q]);
                const float2 f1 = unpack2(o[2 * q + 1]);
                *(float4*)(outp + ch * 16 + q * 4) =
                    make_float4(f0.x, f0.y, f1.x, f1.y);
            }
        }
    }
}

extern "C" void kernel_launch(void* const* d_in, const int* in_sizes, int n_in,
                              void* d_out, int out_size) {
    (void)in_sizes; (void)n_in; (void)out_size;
    const float* X     = (const float*)d_in[0];
    const float* embed = (const float*)d_in[1];
    const float* Wq    = (const float*)d_in[2];
    const float* Wk    = (const float*)d_in[3];

    float* style = (float*)d_out;                              // N*512 floats
    float* attn  = (float*)d_out + (size_t)NBATCH * 512;       // 8*N*10 floats

    precompute_M<<<NCOLS, 256>>>(embed, Wq, Wk);
    fused_attn<<<NBATCH / BM, TPB>>>(X, embed, style, attn);
}

// round 12
// speedup vs baseline: 1.7150x; 1.7150x over previous
#include <cuda_runtime.h>

#define NHEADS 8
#define HDIM   64
#define TNUM   10
#define QDIM   256
#define NCOLS  80        // NHEADS * TNUM
#define NBATCH 131072

#define GPITCH 12            // per-head group pitch (10 used + 2 pad), 4-aligned
#define MPITCH 96            // 8 groups * 12 floats (384B/row)
#define KT     64            // k-tile held in shared
#define NKT    (QDIM / KT)   // 4
#define BROWS  64            // rows per block
#define TPB    256

// Precomputed fused projection matrix in grouped layout:
// M_g[k][h*GPITCH + t],  scores[h,n,t] = sum_k X[n,k] * M[k][h*GPITCH+t]
__device__ float M_g[QDIM * MPITCH];

__global__ void precompute_M(const float* __restrict__ embed,
                             const float* __restrict__ Wq,
                             const float* __restrict__ Wk) {
    const int col = blockIdx.x;          // 0..79
    const int h = col / TNUM;
    const int t = col % TNUM;
    __shared__ float kv[HDIM];
    const int tid = threadIdx.x;         // 0..255
    if (tid < HDIM) {
        const int e = h * HDIM + tid;
        float s = 0.f;
        #pragma unroll
        for (int d = 0; d < HDIM; ++d)
            s += tanhf(embed[t * HDIM + d]) * Wk[e * HDIM + d];
        kv[tid] = s;
    }
    __syncthreads();
    float s = 0.f;
    #pragma unroll
    for (int dd = 0; dd < HDIM; ++dd)
        s += Wq[(h * HDIM + dd) * QDIM + tid] * kv[dd];
    M_g[tid * MPITCH + h * GPITCH + t] = s * 0.125f;
}

// ---- packed f32x2 helpers (FFMA2: 2x fp32 FMA throughput on sm_103a) ----
__device__ __forceinline__ unsigned long long splat2(float x) {
    unsigned long long r;
    asm("mov.b64 %0, {%1, %1};" : "=l"(r) : "r"(__float_as_uint(x)));
    return r;
}
__device__ __forceinline__ void fma2(unsigned long long& d,
                                     unsigned long long a,
                                     unsigned long long b) {
    asm("fma.rn.f32x2 %0, %1, %2, %0;" : "+l"(d) : "l"(a), "l"(b));
}
__device__ __forceinline__ float2 unpack2(unsigned long long v) {
    float lo, hi;
    asm("mov.b64 {%0, %1}, %2;" : "=f"(lo), "=f"(hi) : "l"(v));
    return make_float2(lo, hi);
}

__global__ __launch_bounds__(TPB, 3)
void fused_attn(const float* __restrict__ X,
                const float* __restrict__ embed,
                float* __restrict__ style,   // [N][512]
                float* __restrict__ attn)    // [8][N][10]
{
    // One k-tile of M: 64 x 96 floats = 24KB. No A staging at all:
    // 8 lanes (one per head) share each row -> LDG warp-broadcast + L1 reuse.
    __shared__ __align__(16) float M_sh[KT][MPITCH];
    __shared__ __align__(16) float kr_sh[TNUM * HDIM];

    const int tid = threadIdx.x;
    const int rg = tid >> 3;     // 0..31 : row slot
    const int cg = tid & 7;      // 0..7  : head
    const int rowBase = blockIdx.x * BROWS;
    const size_t n0 = (size_t)rowBase + rg;        // row A
    const size_t n1 = (size_t)rowBase + rg + 32;   // row B

    for (int i = tid; i < TNUM * HDIM; i += TPB)
        kr_sh[i] = tanhf(embed[i]);

    unsigned long long acc0[5], acc1[5];   // 5 col-pairs (10 cols) per row
    #pragma unroll
    for (int j = 0; j < 5; ++j) { acc0[j] = 0ull; acc1[j] = 0ull; }

    for (int t = 0; t < NKT; ++t) {
        __syncthreads();
        // cooperative M tile copy: 1536 float4, 6 per thread, coalesced
        {
            const float4* src = (const float4*)(M_g + t * KT * MPITCH);
            float4* dst = (float4*)&M_sh[0][0];
            #pragma unroll
            for (int j = 0; j < 6; ++j)
                dst[tid + TPB * j] = src[tid + TPB * j];
        }
        __syncthreads();

        const float* x0 = X + n0 * QDIM + t * KT;
        const float* x1 = X + n1 * QDIM + t * KT;

        #pragma unroll 4
        for (int k4 = 0; k4 < KT / 4; ++k4) {
            const float4 a0 = *(const float4*)(x0 + k4 * 4);
            const float4 a1 = *(const float4*)(x1 + k4 * 4);
            #pragma unroll
            for (int j = 0; j < 4; ++j) {
                const float* mrow = &M_sh[k4 * 4 + j][cg * GPITCH];
                const ulonglong2 m01 = *(const ulonglong2*)mrow;
                const ulonglong2 m23 = *(const ulonglong2*)(mrow + 4);
                const unsigned long long m4 = *(const unsigned long long*)(mrow + 8);
                const unsigned long long s0 = splat2(((const float*)&a0)[j]);
                fma2(acc0[0], s0, m01.x);
                fma2(acc0[1], s0, m01.y);
                fma2(acc0[2], s0, m23.x);
                fma2(acc0[3], s0, m23.y);
                fma2(acc0[4], s0, m4);
                const unsigned long long s1 = splat2(((const float*)&a1)[j]);
                fma2(acc1[0], s1, m01.x);
                fma2(acc1[1], s1, m01.y);
                fma2(acc1[2], s1, m23.x);
                fma2(acc1[3], s1, m23.y);
                fma2(acc1[4], s1, m4);
            }
        }
    }

    // ---- epilogue, one row at a time ----
    #pragma unroll
    for (int r = 0; r < 2; ++r) {
        const unsigned long long* acc = r ? acc1 : acc0;
        const size_t n = r ? n1 : n0;

        float s10[10];
        #pragma unroll
        for (int j = 0; j < 5; ++j) {
            const float2 f = unpack2(acc[j]);
            s10[2 * j]     = f.x;
            s10[2 * j + 1] = f.y;
        }

        // attn_score: [h][n][t], h == cg
        float2* ap = (float2*)(attn + (size_t)cg * NBATCH * TNUM + n * TNUM);
        #pragma unroll
        for (int j = 0; j < 5; ++j)
            ap[j] = make_float2(s10[2 * j], s10[2 * j + 1]);

        // style: out[n, cg*64 + d] = sum_t s10[t] * kr[t][d]
        float* outp = style + n * 512 + cg * 64;
        #pragma unroll
        for (int ch = 0; ch < 4; ++ch) {        // 16-float chunks of d
            unsigned long long o[8] = {0ull,0ull,0ull,0ull,0ull,0ull,0ull,0ull};
            #pragma unroll
            for (int t = 0; t < TNUM; ++t) {
                const unsigned long long sv = splat2(s10[t]);
                const float* kp = kr_sh + t * HDIM + ch * 16;
                const ulonglong2 ka = *(const ulonglong2*)kp;
                const ulonglong2 kb = *(const ulonglong2*)(kp + 4);
                const ulonglong2 kc = *(const ulonglong2*)(kp + 8);
                const ulonglong2 kd = *(const ulonglong2*)(kp + 12);
                fma2(o[0], sv, ka.x);
                fma2(o[1], sv, ka.y);
                fma2(o[2], sv, kb.x);
                fma2(o[3], sv, kb.y);
                fma2(o[4], sv, kc.x);
                fma2(o[5], sv, kc.y);
                fma2(o[6], sv, kd.x);
                fma2(o[7], sv, kd.y);
            }
            #pragma unroll
            for (int q = 0; q < 4; ++q) {
                const float2 f0 = unpack2(o[2 * q]);
                const float2 f1 = unpack2(o[2 * q + 1]);
                *(float4*)(outp + ch * 16 + q * 4) =
                    make_float4(f0.x, f0.y, f1.x, f1.y);
            }
        }
    }
}

extern "C" void kernel_launch(void* const* d_in, const int* in_sizes, int n_in,
                              void* d_out, int out_size) {
    (void)in_sizes; (void)n_in; (void)out_size;
    const float* X     = (const float*)d_in[0];
    const float* embed = (const float*)d_in[1];
    const float* Wq    = (const float*)d_in[2];
    const float* Wk    = (const float*)d_in[3];

    float* style = (float*)d_out;                              // N*512 floats
    float* attn  = (float*)d_out + (size_t)NBATCH * 512;       // 8*N*10 floats

    precompute_M<<<NCOLS, 256>>>(embed, Wq, Wk);
    fused_attn<<<NBATCH / BROWS, TPB>>>(X, embed, style, attn);
}